// round 1
// baseline (speedup 1.0000x reference)
#include <cuda_runtime.h>
#include <cuda_bf16.h>
#include <math.h>

// Problem constants
#define BATCH 4
#define SEQ   2048
#define DIM   1024
#define HEADS 16
#define DH    64
#define INNER 1024            // HEADS*DH
#define NFREQ 16
#define ROWS  (BATCH*SEQ)     // 8192
#define BH    (BATCH*HEADS)   // 64

// ---------------- scratch (device globals; no allocation allowed) ----------------
__device__ float g_qkv [(size_t)ROWS * 3 * INNER];   // [8192][3072]
__device__ float g_q   [(size_t)BH * SEQ * DH];      // [bh][n][64]
__device__ float g_k   [(size_t)BH * SEQ * DH];
__device__ float g_v   [(size_t)BH * SEQ * DH];
__device__ float g_attn[(size_t)ROWS * INNER];       // [8192][1024] (b,n,h*d)
__device__ float g_fenc[SEQ * DH];                   // [2048][64]
__device__ float g_sinv[SEQ * 32];
__device__ float g_cosv[SEQ * 32];

// ---------------- table kernel: fenc + rope sin/cos ----------------
__global__ void table_kernel(const float* __restrict__ w_fproj,
                             const float* __restrict__ b_fproj) {
    int p = blockIdx.x;        // 0..2047
    int d = threadIdx.x;       // 0..63
    float fp = (float)p;
    float acc = b_fproj[d];
#pragma unroll
    for (int j = 0; j < NFREQ; j++) {
        float ang = fp * (float)(j + 1);
        float s = sinf(ang);
        float c = cosf(ang);
        acc += s * w_fproj[d * (2 * NFREQ) + j] + c * w_fproj[d * (2 * NFREQ) + NFREQ + j];
    }
    g_fenc[p * DH + d] = acc;
    if (d < 32) {
        // freqs[i] = 10000^(-2i/64)
        float freq = powf(10000.0f, -(float)d / 32.0f);
        float ang = fp * freq;
        g_sinv[p * 32 + d] = sinf(ang);
        g_cosv[p * 32 + d] = cosf(ang);
    }
}

// ---------------- GEMM: C[M][N] = A[M][K] * B[N][K]^T (+bias) ----------------
// classic 128x128 block, BK=8, 8x8 per-thread micro-tile, 256 threads
template<bool BIAS>
__global__ void __launch_bounds__(256)
gemm_nt_kernel(const float* __restrict__ A, const float* __restrict__ Bw,
               const float* __restrict__ bias, float* __restrict__ C,
               int M, int N, int K) {
    __shared__ float As[8][128];
    __shared__ float Bs[8][128];
    const int tid = threadIdx.x;
    const int bm = blockIdx.y * 128;
    const int bn = blockIdx.x * 128;
    const int lr = tid >> 1;            // 0..127
    const int lc = (tid & 1) * 4;       // 0 or 4
    const int trow = (tid >> 4) * 8;
    const int tcol = (tid & 15) * 8;
    float acc[8][8];
#pragma unroll
    for (int i = 0; i < 8; i++)
#pragma unroll
        for (int j = 0; j < 8; j++) acc[i][j] = 0.0f;

    const float* Aptr = A + (size_t)(bm + lr) * K + lc;
    const float* Bptr = Bw + (size_t)(bn + lr) * K + lc;

    for (int k0 = 0; k0 < K; k0 += 8) {
        float4 a4 = *(const float4*)(Aptr + k0);
        float4 b4 = *(const float4*)(Bptr + k0);
        As[lc + 0][lr] = a4.x; As[lc + 1][lr] = a4.y;
        As[lc + 2][lr] = a4.z; As[lc + 3][lr] = a4.w;
        Bs[lc + 0][lr] = b4.x; Bs[lc + 1][lr] = b4.y;
        Bs[lc + 2][lr] = b4.z; Bs[lc + 3][lr] = b4.w;
        __syncthreads();
#pragma unroll
        for (int kk = 0; kk < 8; kk++) {
            float ar[8], br[8];
            *(float4*)&ar[0] = *(const float4*)&As[kk][trow];
            *(float4*)&ar[4] = *(const float4*)&As[kk][trow + 4];
            *(float4*)&br[0] = *(const float4*)&Bs[kk][tcol];
            *(float4*)&br[4] = *(const float4*)&Bs[kk][tcol + 4];
#pragma unroll
            for (int i = 0; i < 8; i++)
#pragma unroll
                for (int j = 0; j < 8; j++)
                    acc[i][j] += ar[i] * br[j];
        }
        __syncthreads();
    }
#pragma unroll
    for (int i = 0; i < 8; i++) {
        float* crow = C + (size_t)(bm + trow + i) * N + bn + tcol;
#pragma unroll
        for (int j = 0; j < 8; j += 4) {
            float4 r4;
            if (BIAS) {
                r4 = make_float4(acc[i][j + 0] + bias[bn + tcol + j + 0],
                                 acc[i][j + 1] + bias[bn + tcol + j + 1],
                                 acc[i][j + 2] + bias[bn + tcol + j + 2],
                                 acc[i][j + 3] + bias[bn + tcol + j + 3]);
            } else {
                r4 = make_float4(acc[i][j + 0], acc[i][j + 1], acc[i][j + 2], acc[i][j + 3]);
            }
            *(float4*)(crow + j) = r4;
        }
    }
}

// ---------------- RoPE + fenc apply + rearrange to head-major ----------------
// thread handles one (b, n, h, d); idx = ((b*SEQ+n)*HEADS+h)*DH+d
__global__ void __launch_bounds__(256)
rope_kernel() {
    int idx = blockIdx.x * 256 + threadIdx.x;   // 0 .. 8388607
    int d = idx & 63;
    int h = (idx >> 6) & 15;
    int n = (idx >> 10) & 2047;
    int b = idx >> 21;
    const float* row = g_qkv + (size_t)(b * SEQ + n) * (3 * INNER);
    int col = h * DH + d;
    float cosv = g_cosv[n * 32 + (d >> 1)];
    float sinv = g_sinv[n * 32 + (d >> 1)];
    float fe   = g_fenc[n * DH + d];
    int pidx; float sgn;
    if (d < 32) { pidx = 2 * d + 1;        sgn = -1.0f; }
    else        { pidx = 2 * (d - 32);     sgn =  1.0f; }
    float qv = row[col];
    float qp = row[h * DH + pidx];
    float kv = row[INNER + col];
    float kp = row[INNER + h * DH + pidx];
    float vv = row[2 * INNER + col];
    int bh = b * HEADS + h;
    size_t o = ((size_t)bh * SEQ + n) * DH + d;
    g_q[o] = qv * cosv + sgn * qp * sinv + fe;
    g_k[o] = kv * cosv + sgn * kp * sinv + fe;
    g_v[o] = vv;
}

// ---------------- flash attention (fp32 SIMT) ----------------
// block = 256 threads (16x16). 64 queries x 64-key tiles, d=64.
// thread (ty,tx): 4 queries (ty*4+u) x 4 keys (tx*4+w) for S,
//                 4 queries x 4 dims (tx*4+i) for O.
// smem: Qt[d][q] (stride 68), KP = Kt[d][k] then Pt[k][q], Vs[k][d].
#define FA_STRIDE 68
#define FA_TILE_F (64 * FA_STRIDE)

__global__ void __launch_bounds__(256)
flash_kernel(float* __restrict__ out) {
    extern __shared__ float sm[];
    float* Qt = sm;
    float* KP = sm + FA_TILE_F;
    float* Vs = sm + 2 * FA_TILE_F;

    const int t = threadIdx.x;
    const int ty = t >> 4;
    const int tx = t & 15;
    const int bh = blockIdx.y;
    const int qt = blockIdx.x;
    const size_t base = (size_t)bh * SEQ * DH;
    const float* qbase = g_q + base + (size_t)qt * 64 * DH;

    // load Q transposed: q = t>>2 (0..63), d0 = (t&3)*16
    {
        int q = t >> 2;
        int d0 = (t & 3) * 16;
#pragma unroll
        for (int j = 0; j < 4; j++) {
            float4 v4 = *(const float4*)&qbase[q * DH + d0 + j * 4];
            Qt[(d0 + j * 4 + 0) * FA_STRIDE + q] = v4.x;
            Qt[(d0 + j * 4 + 1) * FA_STRIDE + q] = v4.y;
            Qt[(d0 + j * 4 + 2) * FA_STRIDE + q] = v4.z;
            Qt[(d0 + j * 4 + 3) * FA_STRIDE + q] = v4.w;
        }
    }

    float m[4], l[4], O[4][4];
#pragma unroll
    for (int u = 0; u < 4; u++) {
        m[u] = -1e30f; l[u] = 0.0f;
#pragma unroll
        for (int i = 0; i < 4; i++) O[u][i] = 0.0f;
    }
    const float scale = 0.125f;   // 64^-0.5

    for (int kt = 0; kt < SEQ / 64; kt++) {
        __syncthreads();   // previous PV done reading KP/Vs
        // load K (transposed) and V (straight)
        {
            int r = t >> 2;
            int d0 = (t & 3) * 16;
            const float* kb = g_k + base + (size_t)(kt * 64 + r) * DH;
            const float* vb = g_v + base + (size_t)(kt * 64 + r) * DH;
#pragma unroll
            for (int j = 0; j < 4; j++) {
                float4 v4 = *(const float4*)&kb[d0 + j * 4];
                KP[(d0 + j * 4 + 0) * FA_STRIDE + r] = v4.x;
                KP[(d0 + j * 4 + 1) * FA_STRIDE + r] = v4.y;
                KP[(d0 + j * 4 + 2) * FA_STRIDE + r] = v4.z;
                KP[(d0 + j * 4 + 3) * FA_STRIDE + r] = v4.w;
            }
#pragma unroll
            for (int j = 0; j < 4; j++) {
                *(float4*)&Vs[r * FA_STRIDE + d0 + j * 4] = *(const float4*)&vb[d0 + j * 4];
            }
        }
        __syncthreads();

        // S = Q K^T (4x4 micro-tile)
        float s[4][4];
#pragma unroll
        for (int u = 0; u < 4; u++)
#pragma unroll
            for (int w = 0; w < 4; w++) s[u][w] = 0.0f;
#pragma unroll 8
        for (int d = 0; d < 64; d++) {
            float4 q4 = *(const float4*)&Qt[d * FA_STRIDE + ty * 4];
            float4 k4 = *(const float4*)&KP[d * FA_STRIDE + tx * 4];
            float qa[4] = {q4.x, q4.y, q4.z, q4.w};
            float ka[4] = {k4.x, k4.y, k4.z, k4.w};
#pragma unroll
            for (int u = 0; u < 4; u++)
#pragma unroll
                for (int w = 0; w < 4; w++) s[u][w] += qa[u] * ka[w];
        }

        // online softmax per query row (replicated across the 16 tx lanes)
#pragma unroll
        for (int u = 0; u < 4; u++) {
            float mx = s[u][0] * scale;
#pragma unroll
            for (int w = 1; w < 4; w++) mx = fmaxf(mx, s[u][w] * scale);
#pragma unroll
            for (int o = 1; o < 16; o <<= 1)
                mx = fmaxf(mx, __shfl_xor_sync(0xffffffffu, mx, o));
            float mn = fmaxf(m[u], mx);
            float corr = __expf(m[u] - mn);
            m[u] = mn;
            float ps = 0.0f;
#pragma unroll
            for (int w = 0; w < 4; w++) {
                float p = __expf(s[u][w] * scale - mn);
                s[u][w] = p;
                ps += p;
            }
#pragma unroll
            for (int o = 1; o < 16; o <<= 1)
                ps += __shfl_xor_sync(0xffffffffu, ps, o);
            l[u] = l[u] * corr + ps;
#pragma unroll
            for (int i = 0; i < 4; i++) O[u][i] *= corr;
        }

        __syncthreads();   // all threads done reading Kt before P overwrites it
        // write P transposed: Pt[k][q]
#pragma unroll
        for (int w = 0; w < 4; w++)
#pragma unroll
            for (int u = 0; u < 4; u++)
                KP[(tx * 4 + w) * FA_STRIDE + ty * 4 + u] = s[u][w];
        __syncthreads();

        // O += P V
#pragma unroll 8
        for (int k = 0; k < 64; k++) {
            float4 p4 = *(const float4*)&KP[k * FA_STRIDE + ty * 4];
            float4 v4 = *(const float4*)&Vs[k * FA_STRIDE + tx * 4];
            float pa[4] = {p4.x, p4.y, p4.z, p4.w};
            float va[4] = {v4.x, v4.y, v4.z, v4.w};
#pragma unroll
            for (int u = 0; u < 4; u++)
#pragma unroll
                for (int i = 0; i < 4; i++) O[u][i] += pa[u] * va[i];
        }
    }

    // epilogue: out[b][n][h*64 + d]
    int b = bh >> 4, h = bh & 15;
#pragma unroll
    for (int u = 0; u < 4; u++) {
        float inv = 1.0f / l[u];
        int row = qt * 64 + ty * 4 + u;
        float* op = out + ((size_t)(b * SEQ + row)) * INNER + h * DH + tx * 4;
        float4 r4 = make_float4(O[u][0] * inv, O[u][1] * inv, O[u][2] * inv, O[u][3] * inv);
        *(float4*)op = r4;
    }
}

// ---------------- launch ----------------
extern "C" void kernel_launch(void* const* d_in, const int* in_sizes, int n_in,
                              void* d_out, int out_size) {
    const float* x       = (const float*)d_in[0];
    const float* w_qkv   = (const float*)d_in[1];
    const float* w_fproj = (const float*)d_in[2];
    const float* b_fproj = (const float*)d_in[3];
    const float* w_out   = (const float*)d_in[4];
    const float* b_out   = (const float*)d_in[5];
    float* out = (float*)d_out;

    float *qkv_p, *attn_p;
    cudaGetSymbolAddress((void**)&qkv_p,  g_qkv);
    cudaGetSymbolAddress((void**)&attn_p, g_attn);

    // 1. tables
    table_kernel<<<SEQ, DH>>>(w_fproj, b_fproj);

    // 2. QKV GEMM: [8192,3072] = x[8192,1024] @ w_qkv[3072,1024]^T
    {
        dim3 grid(3 * INNER / 128, ROWS / 128);
        gemm_nt_kernel<false><<<grid, 256>>>(x, w_qkv, nullptr, qkv_p,
                                             ROWS, 3 * INNER, DIM);
    }

    // 3. RoPE + fenc + rearrange
    rope_kernel<<<(BATCH * SEQ * HEADS * DH) / 256, 256>>>();

    // 4. flash attention
    {
        int smem = 3 * FA_TILE_F * (int)sizeof(float);   // 52224 B
        cudaFuncSetAttribute(flash_kernel, cudaFuncAttributeMaxDynamicSharedMemorySize, smem);
        dim3 grid(SEQ / 64, BH);
        flash_kernel<<<grid, 256, smem>>>(attn_p);
    }

    // 5. out projection: [8192,1024] = attn[8192,1024] @ w_out[1024,1024]^T + b_out
    {
        dim3 grid(DIM / 128, ROWS / 128);
        gemm_nt_kernel<true><<<grid, 256>>>(attn_p, w_out, b_out, out,
                                            ROWS, DIM, INNER);
    }
}

// round 2
// speedup vs baseline: 3.0191x; 3.0191x over previous
#include <cuda_runtime.h>
#include <cuda_bf16.h>
#include <math.h>

// Problem constants
#define BATCH 4
#define SEQ   2048
#define DIM   1024
#define HEADS 16
#define DH    64
#define INNER 1024
#define NFREQ 16
#define ROWS  (BATCH*SEQ)     // 8192
#define BH    (BATCH*HEADS)   // 64

// ---------------- scratch ----------------
__device__ float g_qkv [(size_t)ROWS * 3 * INNER];
__device__ float g_q   [(size_t)BH * SEQ * DH];
__device__ float g_k   [(size_t)BH * SEQ * DH];
__device__ float g_v   [(size_t)BH * SEQ * DH];
__device__ float g_attn[(size_t)ROWS * INNER];
__device__ float g_fenc[SEQ * DH];
__device__ float g_sinv[SEQ * 32];
__device__ float g_cosv[SEQ * 32];

// ---------------- tf32 helpers ----------------
__device__ __forceinline__ unsigned f2t(float x) {
    unsigned u; asm("cvt.rna.tf32.f32 %0, %1;" : "=r"(u) : "f"(x)); return u;
}
__device__ __forceinline__ void mma8(float* c, const unsigned* a, const unsigned* b) {
    asm volatile(
        "mma.sync.aligned.m16n8k8.row.col.f32.tf32.tf32.f32 "
        "{%0,%1,%2,%3},{%4,%5,%6,%7},{%8,%9},{%0,%1,%2,%3};"
        : "+f"(c[0]), "+f"(c[1]), "+f"(c[2]), "+f"(c[3])
        : "r"(a[0]), "r"(a[1]), "r"(a[2]), "r"(a[3]), "r"(b[0]), "r"(b[1]));
}

// ---------------- table kernel ----------------
__global__ void table_kernel(const float* __restrict__ w_fproj,
                             const float* __restrict__ b_fproj) {
    int p = blockIdx.x;
    int d = threadIdx.x;
    float fp = (float)p;
    float acc = b_fproj[d];
#pragma unroll
    for (int j = 0; j < NFREQ; j++) {
        float s = sinf(fp * (float)(j + 1));
        float c = cosf(fp * (float)(j + 1));
        acc += s * w_fproj[d * (2 * NFREQ) + j] + c * w_fproj[d * (2 * NFREQ) + NFREQ + j];
    }
    g_fenc[p * DH + d] = acc;
    if (d < 32) {
        float freq = powf(10000.0f, -(float)d / 32.0f);
        float ang = fp * freq;
        g_sinv[p * 32 + d] = sinf(ang);
        g_cosv[p * 32 + d] = cosf(ang);
    }
}

// ---------------- RoPE + rearrange ----------------
__global__ void __launch_bounds__(256)
rope_kernel() {
    int idx = blockIdx.x * 256 + threadIdx.x;
    int d = idx & 63;
    int h = (idx >> 6) & 15;
    int n = (idx >> 10) & 2047;
    int b = idx >> 21;
    const float* row = g_qkv + (size_t)(b * SEQ + n) * (3 * INNER);
    int col = h * DH + d;
    float cosv = g_cosv[n * 32 + (d >> 1)];
    float sinv = g_sinv[n * 32 + (d >> 1)];
    float fe   = g_fenc[n * DH + d];
    int pidx; float sgn;
    if (d < 32) { pidx = 2 * d + 1;    sgn = -1.0f; }
    else        { pidx = 2 * (d - 32); sgn =  1.0f; }
    float qv = row[col];
    float qp = row[h * DH + pidx];
    float kv = row[INNER + col];
    float kp = row[INNER + h * DH + pidx];
    float vv = row[2 * INNER + col];
    int bh = b * HEADS + h;
    size_t o = ((size_t)bh * SEQ + n) * DH + d;
    g_q[o] = qv * cosv + sgn * qp * sinv + fe;
    g_k[o] = kv * cosv + sgn * kp * sinv + fe;
    g_v[o] = vv;
}

// ---------------- tf32 tensor-core GEMM: C = A[M,K] * Bw[N,K]^T (+bias) ----------------
// 128x128x16 tile, 8 warps (4x2), warp tile 32x64
#define GS 20   // smem stride (conflict-free: row*20 % 32 cycles through distinct banks)

template<bool BIAS>
__global__ void __launch_bounds__(256)
gemm_tf32(const float* __restrict__ A, const float* __restrict__ Bw,
          const float* __restrict__ bias, float* __restrict__ C,
          int M, int N, int K) {
    __shared__ unsigned As[128 * GS];
    __shared__ unsigned Bs[128 * GS];
    const int tid = threadIdx.x;
    const int lane = tid & 31, wid = tid >> 5;
    const int g = lane >> 2, q = lane & 3;
    const int wr = wid >> 1, wc = wid & 1;
    const int bm = blockIdx.y * 128, bn = blockIdx.x * 128;

    float acc[2][8][4];
#pragma unroll
    for (int mt = 0; mt < 2; mt++)
#pragma unroll
        for (int nt = 0; nt < 8; nt++)
#pragma unroll
            for (int i = 0; i < 4; i++) acc[mt][nt][i] = 0.0f;

    for (int k0 = 0; k0 < K; k0 += 16) {
        float4 av[2], bv[2];
#pragma unroll
        for (int j = 0; j < 2; j++) {
            int i = tid + j * 256;
            int row = i >> 2, col = (i & 3) * 4;
            av[j] = *(const float4*)(A  + (size_t)(bm + row) * K + k0 + col);
            bv[j] = *(const float4*)(Bw + (size_t)(bn + row) * K + k0 + col);
        }
        __syncthreads();
#pragma unroll
        for (int j = 0; j < 2; j++) {
            int i = tid + j * 256;
            int row = i >> 2, col = (i & 3) * 4;
            unsigned* ap = &As[row * GS + col];
            ap[0] = f2t(av[j].x); ap[1] = f2t(av[j].y); ap[2] = f2t(av[j].z); ap[3] = f2t(av[j].w);
            unsigned* bp = &Bs[row * GS + col];
            bp[0] = f2t(bv[j].x); bp[1] = f2t(bv[j].y); bp[2] = f2t(bv[j].z); bp[3] = f2t(bv[j].w);
        }
        __syncthreads();

#pragma unroll
        for (int ks = 0; ks < 2; ks++) {
            unsigned af[2][4], bf[8][2];
#pragma unroll
            for (int mt = 0; mt < 2; mt++) {
                int r = wr * 32 + mt * 16;
                af[mt][0] = As[(r + g)     * GS + ks * 8 + q];
                af[mt][1] = As[(r + g + 8) * GS + ks * 8 + q];
                af[mt][2] = As[(r + g)     * GS + ks * 8 + q + 4];
                af[mt][3] = As[(r + g + 8) * GS + ks * 8 + q + 4];
            }
#pragma unroll
            for (int nt = 0; nt < 8; nt++) {
                int c = wc * 64 + nt * 8;
                bf[nt][0] = Bs[(c + g) * GS + ks * 8 + q];
                bf[nt][1] = Bs[(c + g) * GS + ks * 8 + q + 4];
            }
#pragma unroll
            for (int mt = 0; mt < 2; mt++)
#pragma unroll
                for (int nt = 0; nt < 8; nt++)
                    mma8(acc[mt][nt], af[mt], bf[nt]);
        }
    }

#pragma unroll
    for (int mt = 0; mt < 2; mt++) {
        int r = bm + wr * 32 + mt * 16 + g;
#pragma unroll
        for (int nt = 0; nt < 8; nt++) {
            int cc = bn + wc * 64 + nt * 8 + 2 * q;
            float b0 = 0.0f, b1 = 0.0f;
            if (BIAS) { b0 = bias[cc]; b1 = bias[cc + 1]; }
            *(float2*)(C + (size_t)r * N + cc) =
                make_float2(acc[mt][nt][0] + b0, acc[mt][nt][1] + b1);
            *(float2*)(C + (size_t)(r + 8) * N + cc) =
                make_float2(acc[mt][nt][2] + b0, acc[mt][nt][3] + b1);
        }
    }
}

// ---------------- flash attention, tf32 tensor cores ----------------
// block: 128 queries x 1 head; 8 warps, warp owns 16 query rows.
// smem strides chosen conflict-free for each fragment pattern.
#define SQ 68
#define SK 68
#define SV 72
#define SP 68
#define FLASH_SMEM ((128*SQ + 64*SK + 64*SV + 8*16*SP) * 4)

__global__ void __launch_bounds__(256)
flash_tc(float* __restrict__ out) {
    extern __shared__ unsigned sm[];
    unsigned* Qs = sm;                    // [128][SQ]
    unsigned* Ks = Qs + 128 * SQ;         // [64][SK]
    unsigned* Vs = Ks + 64 * SK;          // [64][SV]
    unsigned* Ps = Vs + 64 * SV;          // 8 x [16][SP]

    const int tid = threadIdx.x, lane = tid & 31, wid = tid >> 5;
    const int g = lane >> 2, q = lane & 3;
    const int bh = blockIdx.y, qt = blockIdx.x;
    const size_t base = (size_t)bh * SEQ * DH;
    const float* qg = g_q + base + (size_t)qt * 128 * DH;

    // stage Q (once), fp32 -> tf32
#pragma unroll
    for (int j = 0; j < 8; j++) {
        int i = tid + j * 256;            // 0..2047 float4s
        int row = i >> 4, col = (i & 15) * 4;
        float4 v = *(const float4*)(qg + row * DH + col);
        unsigned* p = &Qs[row * SQ + col];
        p[0] = f2t(v.x); p[1] = f2t(v.y); p[2] = f2t(v.z); p[3] = f2t(v.w);
    }

    float o[8][4];
#pragma unroll
    for (int nt = 0; nt < 8; nt++)
#pragma unroll
        for (int i = 0; i < 4; i++) o[nt][i] = 0.0f;
    float m0 = -1e30f, m1 = -1e30f, l0 = 0.0f, l1 = 0.0f;
    unsigned* Pw = Ps + wid * 16 * SP;
    const int qr = wid * 16;

    for (int kt = 0; kt < SEQ / 64; kt++) {
        __syncthreads();   // prev iter done with Ks/Vs/Ps; also covers Q staging on iter 0
        const float* kg = g_k + base + (size_t)kt * 64 * DH;
        const float* vg = g_v + base + (size_t)kt * 64 * DH;
#pragma unroll
        for (int j = 0; j < 4; j++) {
            int i = tid + j * 256;        // 0..1023 float4s
            int row = i >> 4, col = (i & 15) * 4;
            float4 kv = *(const float4*)(kg + row * DH + col);
            float4 vv = *(const float4*)(vg + row * DH + col);
            unsigned* kp = &Ks[row * SK + col];
            kp[0] = f2t(kv.x); kp[1] = f2t(kv.y); kp[2] = f2t(kv.z); kp[3] = f2t(kv.w);
            unsigned* vp = &Vs[row * SV + col];
            vp[0] = f2t(vv.x); vp[1] = f2t(vv.y); vp[2] = f2t(vv.z); vp[3] = f2t(vv.w);
        }
        __syncthreads();

        // S = Q K^T  (warp: 16 x 64)
        float s[8][4];
#pragma unroll
        for (int nt = 0; nt < 8; nt++)
#pragma unroll
            for (int i = 0; i < 4; i++) s[nt][i] = 0.0f;
#pragma unroll
        for (int kc = 0; kc < 8; kc++) {
            unsigned af[4];
            af[0] = Qs[(qr + g)     * SQ + kc * 8 + q];
            af[1] = Qs[(qr + g + 8) * SQ + kc * 8 + q];
            af[2] = Qs[(qr + g)     * SQ + kc * 8 + q + 4];
            af[3] = Qs[(qr + g + 8) * SQ + kc * 8 + q + 4];
#pragma unroll
            for (int nt = 0; nt < 8; nt++) {
                unsigned bf[2];
                bf[0] = Ks[(nt * 8 + g) * SK + kc * 8 + q];
                bf[1] = Ks[(nt * 8 + g) * SK + kc * 8 + q + 4];
                mma8(s[nt], af, bf);
            }
        }

        // online softmax (rows g and g+8; quad = 4 lanes share a row)
        const float sc = 0.125f;
        float rm0 = -1e30f, rm1 = -1e30f;
#pragma unroll
        for (int nt = 0; nt < 8; nt++) {
            s[nt][0] *= sc; s[nt][1] *= sc; s[nt][2] *= sc; s[nt][3] *= sc;
            rm0 = fmaxf(rm0, fmaxf(s[nt][0], s[nt][1]));
            rm1 = fmaxf(rm1, fmaxf(s[nt][2], s[nt][3]));
        }
        rm0 = fmaxf(rm0, __shfl_xor_sync(0xffffffffu, rm0, 1));
        rm0 = fmaxf(rm0, __shfl_xor_sync(0xffffffffu, rm0, 2));
        rm1 = fmaxf(rm1, __shfl_xor_sync(0xffffffffu, rm1, 1));
        rm1 = fmaxf(rm1, __shfl_xor_sync(0xffffffffu, rm1, 2));
        float mn0 = fmaxf(m0, rm0), mn1 = fmaxf(m1, rm1);
        float c0 = __expf(m0 - mn0), c1 = __expf(m1 - mn1);
        m0 = mn0; m1 = mn1;
        float rs0 = 0.0f, rs1 = 0.0f;
#pragma unroll
        for (int nt = 0; nt < 8; nt++) {
            s[nt][0] = __expf(s[nt][0] - mn0);
            s[nt][1] = __expf(s[nt][1] - mn0);
            s[nt][2] = __expf(s[nt][2] - mn1);
            s[nt][3] = __expf(s[nt][3] - mn1);
            rs0 += s[nt][0] + s[nt][1];
            rs1 += s[nt][2] + s[nt][3];
        }
        rs0 += __shfl_xor_sync(0xffffffffu, rs0, 1);
        rs0 += __shfl_xor_sync(0xffffffffu, rs0, 2);
        rs1 += __shfl_xor_sync(0xffffffffu, rs1, 1);
        rs1 += __shfl_xor_sync(0xffffffffu, rs1, 2);
        l0 = l0 * c0 + rs0;
        l1 = l1 * c1 + rs1;
#pragma unroll
        for (int nt = 0; nt < 8; nt++) {
            o[nt][0] *= c0; o[nt][1] *= c0; o[nt][2] *= c1; o[nt][3] *= c1;
        }

        // P -> per-warp smem (C-layout -> A-layout bridge)
#pragma unroll
        for (int nt = 0; nt < 8; nt++) {
            Pw[g * SP + nt * 8 + 2 * q]           = f2t(s[nt][0]);
            Pw[g * SP + nt * 8 + 2 * q + 1]       = f2t(s[nt][1]);
            Pw[(g + 8) * SP + nt * 8 + 2 * q]     = f2t(s[nt][2]);
            Pw[(g + 8) * SP + nt * 8 + 2 * q + 1] = f2t(s[nt][3]);
        }
        __syncwarp();

        // O += P V  (warp: 16 x 64, k = 64 keys)
#pragma unroll
        for (int kc = 0; kc < 8; kc++) {
            unsigned af[4];
            af[0] = Pw[g * SP + kc * 8 + q];
            af[1] = Pw[(g + 8) * SP + kc * 8 + q];
            af[2] = Pw[g * SP + kc * 8 + q + 4];
            af[3] = Pw[(g + 8) * SP + kc * 8 + q + 4];
#pragma unroll
            for (int nt = 0; nt < 8; nt++) {
                unsigned bf[2];
                bf[0] = Vs[(kc * 8 + q)     * SV + nt * 8 + g];
                bf[1] = Vs[(kc * 8 + q + 4) * SV + nt * 8 + g];
                mma8(o[nt], af, bf);
            }
        }
    }

    // epilogue
    int b = bh >> 4, h = bh & 15;
    float il0 = 1.0f / l0, il1 = 1.0f / l1;
    int r0 = qt * 128 + qr + g;
#pragma unroll
    for (int nt = 0; nt < 8; nt++) {
        int cc = h * DH + nt * 8 + 2 * q;
        *(float2*)(out + (size_t)(b * SEQ + r0) * INNER + cc) =
            make_float2(o[nt][0] * il0, o[nt][1] * il0);
        *(float2*)(out + (size_t)(b * SEQ + r0 + 8) * INNER + cc) =
            make_float2(o[nt][2] * il1, o[nt][3] * il1);
    }
}

// ---------------- launch ----------------
extern "C" void kernel_launch(void* const* d_in, const int* in_sizes, int n_in,
                              void* d_out, int out_size) {
    const float* x       = (const float*)d_in[0];
    const float* w_qkv   = (const float*)d_in[1];
    const float* w_fproj = (const float*)d_in[2];
    const float* b_fproj = (const float*)d_in[3];
    const float* w_out   = (const float*)d_in[4];
    const float* b_out   = (const float*)d_in[5];
    float* out = (float*)d_out;

    float *qkv_p, *attn_p;
    cudaGetSymbolAddress((void**)&qkv_p,  g_qkv);
    cudaGetSymbolAddress((void**)&attn_p, g_attn);

    table_kernel<<<SEQ, DH>>>(w_fproj, b_fproj);

    {   // QKV: [8192,3072] = x[8192,1024] @ w_qkv[3072,1024]^T
        dim3 grid(3 * INNER / 128, ROWS / 128);
        gemm_tf32<false><<<grid, 256>>>(x, w_qkv, nullptr, qkv_p, ROWS, 3 * INNER, DIM);
    }

    rope_kernel<<<(BATCH * SEQ * HEADS * DH) / 256, 256>>>();

    {   // flash attention
        static int cfg_done = 0;
        cudaFuncSetAttribute(flash_tc, cudaFuncAttributeMaxDynamicSharedMemorySize, FLASH_SMEM);
        (void)cfg_done;
        dim3 grid(SEQ / 128, BH);
        flash_tc<<<grid, 256, FLASH_SMEM>>>(attn_p);
    }

    {   // out projection
        dim3 grid(DIM / 128, ROWS / 128);
        gemm_tf32<true><<<grid, 256>>>(attn_p, w_out, b_out, out, ROWS, DIM, INNER);
    }
}

// round 3
// speedup vs baseline: 3.4682x; 1.1487x over previous
#include <cuda_runtime.h>
#include <cuda_bf16.h>
#include <math.h>

#define BATCH 4
#define SEQ   2048
#define DIM   1024
#define HEADS 16
#define DH    64
#define INNER 1024
#define NFREQ 16
#define ROWS  (BATCH*SEQ)     // 8192
#define BH    (BATCH*HEADS)   // 64

// ---------------- scratch ----------------
__device__ float g_qkv [(size_t)ROWS * 3 * INNER];
__device__ float g_q   [(size_t)BH * SEQ * DH];
__device__ float g_k   [(size_t)BH * SEQ * DH];
__device__ float g_v   [(size_t)BH * SEQ * DH];
__device__ float g_attn[(size_t)ROWS * INNER];
__device__ float g_fenc[SEQ * DH];
__device__ float g_sinv[SEQ * 32];
__device__ float g_cosv[SEQ * 32];

// ---------------- helpers ----------------
__device__ __forceinline__ unsigned f2t(float x) {
    unsigned u; asm("cvt.rna.tf32.f32 %0, %1;" : "=r"(u) : "f"(x)); return u;
}
__device__ __forceinline__ void mma8(float* c, const unsigned* a, const unsigned* b) {
    asm volatile(
        "mma.sync.aligned.m16n8k8.row.col.f32.tf32.tf32.f32 "
        "{%0,%1,%2,%3},{%4,%5,%6,%7},{%8,%9},{%0,%1,%2,%3};"
        : "+f"(c[0]), "+f"(c[1]), "+f"(c[2]), "+f"(c[3])
        : "r"(a[0]), "r"(a[1]), "r"(a[2]), "r"(a[3]), "r"(b[0]), "r"(b[1]));
}
__device__ __forceinline__ void cpa16(void* smem, const void* gmem) {
    unsigned s = (unsigned)__cvta_generic_to_shared(smem);
    asm volatile("cp.async.cg.shared.global [%0], [%1], 16;" :: "r"(s), "l"(gmem));
}
__device__ __forceinline__ void cpa_commit() { asm volatile("cp.async.commit_group;"); }
template<int N> __device__ __forceinline__ void cpa_wait() {
    asm volatile("cp.async.wait_group %0;" :: "n"(N));
}

// ---------------- table kernel ----------------
__global__ void table_kernel(const float* __restrict__ w_fproj,
                             const float* __restrict__ b_fproj) {
    int p = blockIdx.x;
    int d = threadIdx.x;
    float fp = (float)p;
    float acc = b_fproj[d];
#pragma unroll
    for (int j = 0; j < NFREQ; j++) {
        float s = sinf(fp * (float)(j + 1));
        float c = cosf(fp * (float)(j + 1));
        acc += s * w_fproj[d * (2 * NFREQ) + j] + c * w_fproj[d * (2 * NFREQ) + NFREQ + j];
    }
    g_fenc[p * DH + d] = acc;
    if (d < 32) {
        float freq = powf(10000.0f, -(float)d / 32.0f);
        float ang = fp * freq;
        g_sinv[p * 32 + d] = sinf(ang);
        g_cosv[p * 32 + d] = cosf(ang);
    }
}

// ---------------- RoPE + rearrange ----------------
__global__ void __launch_bounds__(256)
rope_kernel() {
    int idx = blockIdx.x * 256 + threadIdx.x;
    int d = idx & 63;
    int h = (idx >> 6) & 15;
    int n = (idx >> 10) & 2047;
    int b = idx >> 21;
    const float* row = g_qkv + (size_t)(b * SEQ + n) * (3 * INNER);
    int col = h * DH + d;
    float cosv = g_cosv[n * 32 + (d >> 1)];
    float sinv = g_sinv[n * 32 + (d >> 1)];
    float fe   = g_fenc[n * DH + d];
    int pidx; float sgn;
    if (d < 32) { pidx = 2 * d + 1;    sgn = -1.0f; }
    else        { pidx = 2 * (d - 32); sgn =  1.0f; }
    float qv = row[col];
    float qp = row[h * DH + pidx];
    float kv = row[INNER + col];
    float kp = row[INNER + h * DH + pidx];
    float vv = row[2 * INNER + col];
    int bh = b * HEADS + h;
    size_t o = ((size_t)bh * SEQ + n) * DH + d;
    g_q[o] = qv * cosv + sgn * qp * sinv + fe;
    g_k[o] = kv * cosv + sgn * kp * sinv + fe;
    g_v[o] = vv;
}

// ---------------- tf32 GEMM, cp.async double-buffered ----------------
// C = A[M,K] * Bw[N,K]^T (+bias). 128x128x16 tile, 8 warps (4x2), warp 32x64.
#define GS 20
#define GEMM_SMEM (2 * 2 * 128 * GS * 4)   // 81920 B

template<bool BIAS>
__global__ void __launch_bounds__(256, 2)
gemm_tf32(const float* __restrict__ A, const float* __restrict__ Bw,
          const float* __restrict__ bias, float* __restrict__ C,
          int M, int N, int K) {
    extern __shared__ float gsm[];
    float* As = gsm;                 // [2][128*GS]
    float* Bs = gsm + 2 * 128 * GS;  // [2][128*GS]
    const int tid = threadIdx.x;
    const int lane = tid & 31, wid = tid >> 5;
    const int g = lane >> 2, q = lane & 3;
    const int wr = wid >> 1, wc = wid & 1;
    const int bm = blockIdx.y * 128, bn = blockIdx.x * 128;
    const int lrow = tid >> 2, lcol = (tid & 3) * 4;   // loader: 2 passes cover 128x16
    const int lrow2 = lrow + 64;

    float acc[2][8][4];
#pragma unroll
    for (int mt = 0; mt < 2; mt++)
#pragma unroll
        for (int nt = 0; nt < 8; nt++)
#pragma unroll
            for (int i = 0; i < 4; i++) acc[mt][nt][i] = 0.0f;

    // stage k-tile k0 into buffer `buf`
    auto stage = [&](int buf, int k0) {
        float* ab = As + buf * 128 * GS;
        float* bb = Bs + buf * 128 * GS;
        cpa16(ab + lrow  * GS + lcol, A  + (size_t)(bm + lrow)  * K + k0 + lcol);
        cpa16(ab + lrow2 * GS + lcol, A  + (size_t)(bm + lrow2) * K + k0 + lcol);
        cpa16(bb + lrow  * GS + lcol, Bw + (size_t)(bn + lrow)  * K + k0 + lcol);
        cpa16(bb + lrow2 * GS + lcol, Bw + (size_t)(bn + lrow2) * K + k0 + lcol);
        cpa_commit();
    };

    stage(0, 0);
    for (int k0 = 0; k0 < K; k0 += 16) {
        int cur = (k0 >> 4) & 1;
        if (k0 + 16 < K) { stage(cur ^ 1, k0 + 16); cpa_wait<1>(); }
        else             { cpa_wait<0>(); }
        __syncthreads();
        const float* ab = As + cur * 128 * GS;
        const float* bb = Bs + cur * 128 * GS;
#pragma unroll
        for (int ks = 0; ks < 2; ks++) {
            unsigned af[2][4], bf[8][2];
#pragma unroll
            for (int mt = 0; mt < 2; mt++) {
                int r = wr * 32 + mt * 16;
                af[mt][0] = f2t(ab[(r + g)     * GS + ks * 8 + q]);
                af[mt][1] = f2t(ab[(r + g + 8) * GS + ks * 8 + q]);
                af[mt][2] = f2t(ab[(r + g)     * GS + ks * 8 + q + 4]);
                af[mt][3] = f2t(ab[(r + g + 8) * GS + ks * 8 + q + 4]);
            }
#pragma unroll
            for (int nt = 0; nt < 8; nt++) {
                int c = wc * 64 + nt * 8;
                bf[nt][0] = f2t(bb[(c + g) * GS + ks * 8 + q]);
                bf[nt][1] = f2t(bb[(c + g) * GS + ks * 8 + q + 4]);
            }
#pragma unroll
            for (int mt = 0; mt < 2; mt++)
#pragma unroll
                for (int nt = 0; nt < 8; nt++)
                    mma8(acc[mt][nt], af[mt], bf[nt]);
        }
        __syncthreads();
    }

#pragma unroll
    for (int mt = 0; mt < 2; mt++) {
        int r = bm + wr * 32 + mt * 16 + g;
#pragma unroll
        for (int nt = 0; nt < 8; nt++) {
            int cc = bn + wc * 64 + nt * 8 + 2 * q;
            float b0 = 0.0f, b1 = 0.0f;
            if (BIAS) { b0 = bias[cc]; b1 = bias[cc + 1]; }
            *(float2*)(C + (size_t)r * N + cc) =
                make_float2(acc[mt][nt][0] + b0, acc[mt][nt][1] + b1);
            *(float2*)(C + (size_t)(r + 8) * N + cc) =
                make_float2(acc[mt][nt][2] + b0, acc[mt][nt][3] + b1);
        }
    }
}

// ---------------- flash attention v3 ----------------
// 128 queries x 1 head per block; 8 warps x 16 rows. K/V cp.async double-buffered
// (raw fp32, cvt at fragment load). P bridged C->A layout via shfl (no smem).
#define SQ 68
#define SK 68
#define SV 72
#define NT (SEQ / 64)
#define FLASH_SMEM ((128*SQ + 2*64*SK + 2*64*SV) * 4)   // 106496 B

__global__ void __launch_bounds__(256, 2)
flash_tc(float* __restrict__ out) {
    extern __shared__ char smraw[];
    unsigned* Qs = (unsigned*)smraw;                 // [128][SQ] tf32
    float* Kb = (float*)(smraw + 128 * SQ * 4);      // [2][64*SK] fp32
    float* Vb = Kb + 2 * 64 * SK;                    // [2][64*SV] fp32

    const int tid = threadIdx.x, lane = tid & 31, wid = tid >> 5;
    const int g = lane >> 2, q = lane & 3;
    const int bh = blockIdx.y, qt = blockIdx.x;
    const size_t base = (size_t)bh * SEQ * DH;
    const float* qg = g_q + base + (size_t)qt * 128 * DH;
    const float* kg0 = g_k + base;
    const float* vg0 = g_v + base;
    const int lrow = tid >> 4, lcol = (tid & 15) * 4;   // 4 passes cover 64x64

    // stage Q once (tf32)
#pragma unroll
    for (int j = 0; j < 8; j++) {
        int i = tid + j * 256;
        int row = i >> 4, col = (i & 15) * 4;
        float4 v = *(const float4*)(qg + row * DH + col);
        unsigned* p = &Qs[row * SQ + col];
        p[0] = f2t(v.x); p[1] = f2t(v.y); p[2] = f2t(v.z); p[3] = f2t(v.w);
    }

    auto stage = [&](int buf, int kt) {
        float* kb = Kb + buf * 64 * SK;
        float* vb = Vb + buf * 64 * SV;
        const float* kg = kg0 + (size_t)kt * 64 * DH;
        const float* vg = vg0 + (size_t)kt * 64 * DH;
#pragma unroll
        for (int j = 0; j < 4; j++) {
            int row = lrow + j * 16;
            cpa16(kb + row * SK + lcol, kg + row * DH + lcol);
            cpa16(vb + row * SV + lcol, vg + row * DH + lcol);
        }
        cpa_commit();
    };

    float o[8][4];
#pragma unroll
    for (int nt = 0; nt < 8; nt++)
#pragma unroll
        for (int i = 0; i < 4; i++) o[nt][i] = 0.0f;
    float m0 = -1e30f, m1 = -1e30f, l0 = 0.0f, l1 = 0.0f;
    const int qr = wid * 16;
    const int srcA = (lane & ~3) + (q >> 1);
    const int srcB = srcA + 2;
    const bool odd = q & 1;

    stage(0, 0);
    for (int kt = 0; kt < NT; kt++) {
        int cur = kt & 1;
        if (kt + 1 < NT) { stage(cur ^ 1, kt + 1); cpa_wait<1>(); }
        else             { cpa_wait<0>(); }
        __syncthreads();
        const float* kb = Kb + cur * 64 * SK;
        const float* vb = Vb + cur * 64 * SV;

        // S = Q K^T (warp: 16x64)
        float s[8][4];
#pragma unroll
        for (int nt = 0; nt < 8; nt++)
#pragma unroll
            for (int i = 0; i < 4; i++) s[nt][i] = 0.0f;
#pragma unroll
        for (int kc = 0; kc < 8; kc++) {
            unsigned af[4];
            af[0] = Qs[(qr + g)     * SQ + kc * 8 + q];
            af[1] = Qs[(qr + g + 8) * SQ + kc * 8 + q];
            af[2] = Qs[(qr + g)     * SQ + kc * 8 + q + 4];
            af[3] = Qs[(qr + g + 8) * SQ + kc * 8 + q + 4];
#pragma unroll
            for (int nt = 0; nt < 8; nt++) {
                unsigned bf[2];
                bf[0] = f2t(kb[(nt * 8 + g) * SK + kc * 8 + q]);
                bf[1] = f2t(kb[(nt * 8 + g) * SK + kc * 8 + q + 4]);
                mma8(s[nt], af, bf);
            }
        }

        // online softmax
        const float sc = 0.125f;
        float rm0 = -1e30f, rm1 = -1e30f;
#pragma unroll
        for (int nt = 0; nt < 8; nt++) {
            s[nt][0] *= sc; s[nt][1] *= sc; s[nt][2] *= sc; s[nt][3] *= sc;
            rm0 = fmaxf(rm0, fmaxf(s[nt][0], s[nt][1]));
            rm1 = fmaxf(rm1, fmaxf(s[nt][2], s[nt][3]));
        }
        rm0 = fmaxf(rm0, __shfl_xor_sync(0xffffffffu, rm0, 1));
        rm0 = fmaxf(rm0, __shfl_xor_sync(0xffffffffu, rm0, 2));
        rm1 = fmaxf(rm1, __shfl_xor_sync(0xffffffffu, rm1, 1));
        rm1 = fmaxf(rm1, __shfl_xor_sync(0xffffffffu, rm1, 2));
        float mn0 = fmaxf(m0, rm0), mn1 = fmaxf(m1, rm1);
        float c0 = __expf(m0 - mn0), c1 = __expf(m1 - mn1);
        m0 = mn0; m1 = mn1;
        float rs0 = 0.0f, rs1 = 0.0f;
#pragma unroll
        for (int nt = 0; nt < 8; nt++) {
            s[nt][0] = __expf(s[nt][0] - mn0);
            s[nt][1] = __expf(s[nt][1] - mn0);
            s[nt][2] = __expf(s[nt][2] - mn1);
            s[nt][3] = __expf(s[nt][3] - mn1);
            rs0 += s[nt][0] + s[nt][1];
            rs1 += s[nt][2] + s[nt][3];
        }
        rs0 += __shfl_xor_sync(0xffffffffu, rs0, 1);
        rs0 += __shfl_xor_sync(0xffffffffu, rs0, 2);
        rs1 += __shfl_xor_sync(0xffffffffu, rs1, 1);
        rs1 += __shfl_xor_sync(0xffffffffu, rs1, 2);
        l0 = l0 * c0 + rs0;
        l1 = l1 * c1 + rs1;
#pragma unroll
        for (int nt = 0; nt < 8; nt++) {
            o[nt][0] *= c0; o[nt][1] *= c0; o[nt][2] *= c1; o[nt][3] *= c1;
        }

        // O += P V  — P fragments built by shfl (C-layout -> A-layout)
#pragma unroll
        for (int kc = 0; kc < 8; kc++) {
            float e0 = __shfl_sync(0xffffffffu, s[kc][0], srcA);
            float e1 = __shfl_sync(0xffffffffu, s[kc][1], srcA);
            float e2 = __shfl_sync(0xffffffffu, s[kc][2], srcA);
            float e3 = __shfl_sync(0xffffffffu, s[kc][3], srcA);
            float f0 = __shfl_sync(0xffffffffu, s[kc][0], srcB);
            float f1 = __shfl_sync(0xffffffffu, s[kc][1], srcB);
            float f2 = __shfl_sync(0xffffffffu, s[kc][2], srcB);
            float f3 = __shfl_sync(0xffffffffu, s[kc][3], srcB);
            unsigned af[4];
            af[0] = f2t(odd ? e1 : e0);
            af[1] = f2t(odd ? e3 : e2);
            af[2] = f2t(odd ? f1 : f0);
            af[3] = f2t(odd ? f3 : f2);
#pragma unroll
            for (int nt = 0; nt < 8; nt++) {
                unsigned bf[2];
                bf[0] = f2t(vb[(kc * 8 + q)     * SV + nt * 8 + g]);
                bf[1] = f2t(vb[(kc * 8 + q + 4) * SV + nt * 8 + g]);
                mma8(o[nt], af, bf);
            }
        }
        __syncthreads();
    }

    // epilogue
    int b = bh >> 4, h = bh & 15;
    float il0 = 1.0f / l0, il1 = 1.0f / l1;
    int r0 = qt * 128 + qr + g;
#pragma unroll
    for (int nt = 0; nt < 8; nt++) {
        int cc = h * DH + nt * 8 + 2 * q;
        *(float2*)(out + (size_t)(b * SEQ + r0) * INNER + cc) =
            make_float2(o[nt][0] * il0, o[nt][1] * il0);
        *(float2*)(out + (size_t)(b * SEQ + r0 + 8) * INNER + cc) =
            make_float2(o[nt][2] * il1, o[nt][3] * il1);
    }
}

// ---------------- launch ----------------
extern "C" void kernel_launch(void* const* d_in, const int* in_sizes, int n_in,
                              void* d_out, int out_size) {
    const float* x       = (const float*)d_in[0];
    const float* w_qkv   = (const float*)d_in[1];
    const float* w_fproj = (const float*)d_in[2];
    const float* b_fproj = (const float*)d_in[3];
    const float* w_out   = (const float*)d_in[4];
    const float* b_out   = (const float*)d_in[5];
    float* out = (float*)d_out;

    float *qkv_p, *attn_p;
    cudaGetSymbolAddress((void**)&qkv_p,  g_qkv);
    cudaGetSymbolAddress((void**)&attn_p, g_attn);

    cudaFuncSetAttribute(gemm_tf32<false>, cudaFuncAttributeMaxDynamicSharedMemorySize, GEMM_SMEM);
    cudaFuncSetAttribute(gemm_tf32<true>,  cudaFuncAttributeMaxDynamicSharedMemorySize, GEMM_SMEM);
    cudaFuncSetAttribute(flash_tc, cudaFuncAttributeMaxDynamicSharedMemorySize, FLASH_SMEM);

    table_kernel<<<SEQ, DH>>>(w_fproj, b_fproj);

    {   // QKV: [8192,3072] = x @ w_qkv^T
        dim3 grid(3 * INNER / 128, ROWS / 128);
        gemm_tf32<false><<<grid, 256, GEMM_SMEM>>>(x, w_qkv, nullptr, qkv_p, ROWS, 3 * INNER, DIM);
    }

    rope_kernel<<<(BATCH * SEQ * HEADS * DH) / 256, 256>>>();

    {   // flash attention
        dim3 grid(SEQ / 128, BH);
        flash_tc<<<grid, 256, FLASH_SMEM>>>(attn_p);
    }

    {   // out projection
        dim3 grid(DIM / 128, ROWS / 128);
        gemm_tf32<true><<<grid, 256, GEMM_SMEM>>>(attn_p, w_out, b_out, out, ROWS, DIM, INNER);
    }
}

// round 5
// speedup vs baseline: 3.6919x; 1.0645x over previous
#include <cuda_runtime.h>
#include <cuda_bf16.h>
#include <math.h>
#include <cstdint>

#define BATCH 4
#define SEQ   2048
#define DIM   1024
#define HEADS 16
#define DH    64
#define INNER 1024
#define NFREQ 16
#define ROWS  (BATCH*SEQ)     // 8192
#define BH    (BATCH*HEADS)   // 64

// ---------------- scratch ----------------
__device__ float g_qkv [(size_t)ROWS * 3 * INNER];
__device__ float g_q   [(size_t)BH * SEQ * DH];   // tf32-rounded, pre-scaled by 1/8
__device__ float g_k   [(size_t)BH * SEQ * DH];   // tf32-rounded
__device__ float g_v   [(size_t)BH * SEQ * DH];   // tf32-rounded
__device__ float g_attn[(size_t)ROWS * INNER];
__device__ float g_fenc[SEQ * DH];
__device__ float g_sinv[SEQ * 32];
__device__ float g_cosv[SEQ * 32];

// ---------------- helpers ----------------
__device__ __forceinline__ unsigned f2t(float x) {
    unsigned u; asm("cvt.rna.tf32.f32 %0, %1;" : "=r"(u) : "f"(x)); return u;
}
__device__ __forceinline__ void mma8(float* c, const unsigned* a, const unsigned* b) {
    asm volatile(
        "mma.sync.aligned.m16n8k8.row.col.f32.tf32.tf32.f32 "
        "{%0,%1,%2,%3},{%4,%5,%6,%7},{%8,%9},{%0,%1,%2,%3};"
        : "+f"(c[0]), "+f"(c[1]), "+f"(c[2]), "+f"(c[3])
        : "r"(a[0]), "r"(a[1]), "r"(a[2]), "r"(a[3]), "r"(b[0]), "r"(b[1]));
}
__device__ __forceinline__ void cpa16(void* smem, const void* gmem) {
    unsigned s = (unsigned)__cvta_generic_to_shared(smem);
    asm volatile("cp.async.cg.shared.global [%0], [%1], 16;" :: "r"(s), "l"(gmem));
}
__device__ __forceinline__ void cpa_commit() { asm volatile("cp.async.commit_group;"); }
template<int N> __device__ __forceinline__ void cpa_wait() {
    asm volatile("cp.async.wait_group %0;" :: "n"(N));
}

// ---------------- table kernel ----------------
__global__ void table_kernel(const float* __restrict__ w_fproj,
                             const float* __restrict__ b_fproj) {
    int p = blockIdx.x;
    int d = threadIdx.x;
    float fp = (float)p;
    float acc = b_fproj[d];
#pragma unroll
    for (int j = 0; j < NFREQ; j++) {
        float s = sinf(fp * (float)(j + 1));
        float c = cosf(fp * (float)(j + 1));
        acc += s * w_fproj[d * (2 * NFREQ) + j] + c * w_fproj[d * (2 * NFREQ) + NFREQ + j];
    }
    g_fenc[p * DH + d] = acc;
    if (d < 32) {
        float freq = powf(10000.0f, -(float)d / 32.0f);
        float ang = fp * freq;
        g_sinv[p * 32 + d] = sinf(ang);
        g_cosv[p * 32 + d] = cosf(ang);
    }
}

// ---------------- RoPE + rearrange + tf32 pre-round ----------------
__global__ void __launch_bounds__(256)
rope_kernel() {
    int idx = blockIdx.x * 256 + threadIdx.x;
    int d = idx & 63;
    int h = (idx >> 6) & 15;
    int n = (idx >> 10) & 2047;
    int b = idx >> 21;
    const float* row = g_qkv + (size_t)(b * SEQ + n) * (3 * INNER);
    int col = h * DH + d;
    float cosv = g_cosv[n * 32 + (d >> 1)];
    float sinv = g_sinv[n * 32 + (d >> 1)];
    float fe   = g_fenc[n * DH + d];
    int pidx; float sgn;
    if (d < 32) { pidx = 2 * d + 1;    sgn = -1.0f; }
    else        { pidx = 2 * (d - 32); sgn =  1.0f; }
    float qv = row[col];
    float qp = row[h * DH + pidx];
    float kv = row[INNER + col];
    float kp = row[INNER + h * DH + pidx];
    float vv = row[2 * INNER + col];
    int bh = b * HEADS + h;
    size_t o = ((size_t)bh * SEQ + n) * DH + d;
    // q carries the softmax scale (1/8) folded in; all three pre-rounded to tf32
    g_q[o] = __uint_as_float(f2t(0.125f * (qv * cosv + sgn * qp * sinv + fe)));
    g_k[o] = __uint_as_float(f2t(kv * cosv + sgn * kp * sinv + fe));
    g_v[o] = __uint_as_float(f2t(vv));
}

// ---------------- tf32 GEMM, cp.async double-buffered (R3-proven) ----------------
#define GS 20
#define GEMM_SMEM (2 * 2 * 128 * GS * 4)   // 81920 B

template<bool BIAS>
__global__ void __launch_bounds__(256, 2)
gemm_tf32(const float* __restrict__ A, const float* __restrict__ Bw,
          const float* __restrict__ bias, float* __restrict__ C,
          int M, int N, int K) {
    extern __shared__ float gsm[];
    float* As = gsm;
    float* Bs = gsm + 2 * 128 * GS;
    const int tid = threadIdx.x;
    const int lane = tid & 31, wid = tid >> 5;
    const int g = lane >> 2, q = lane & 3;
    const int wr = wid >> 1, wc = wid & 1;
    const int bm = blockIdx.y * 128, bn = blockIdx.x * 128;
    const int lrow = tid >> 2, lcol = (tid & 3) * 4;
    const int lrow2 = lrow + 64;

    float acc[2][8][4];
#pragma unroll
    for (int mt = 0; mt < 2; mt++)
#pragma unroll
        for (int nt = 0; nt < 8; nt++)
#pragma unroll
            for (int i = 0; i < 4; i++) acc[mt][nt][i] = 0.0f;

    auto stage = [&](int buf, int k0) {
        float* ab = As + buf * 128 * GS;
        float* bb = Bs + buf * 128 * GS;
        cpa16(ab + lrow  * GS + lcol, A  + (size_t)(bm + lrow)  * K + k0 + lcol);
        cpa16(ab + lrow2 * GS + lcol, A  + (size_t)(bm + lrow2) * K + k0 + lcol);
        cpa16(bb + lrow  * GS + lcol, Bw + (size_t)(bn + lrow)  * K + k0 + lcol);
        cpa16(bb + lrow2 * GS + lcol, Bw + (size_t)(bn + lrow2) * K + k0 + lcol);
        cpa_commit();
    };

    stage(0, 0);
    for (int k0 = 0; k0 < K; k0 += 16) {
        int cur = (k0 >> 4) & 1;
        if (k0 + 16 < K) { stage(cur ^ 1, k0 + 16); cpa_wait<1>(); }
        else             { cpa_wait<0>(); }
        __syncthreads();
        const float* ab = As + cur * 128 * GS;
        const float* bb = Bs + cur * 128 * GS;
#pragma unroll
        for (int ks = 0; ks < 2; ks++) {
            unsigned af[2][4], bf[8][2];
#pragma unroll
            for (int mt = 0; mt < 2; mt++) {
                int r = wr * 32 + mt * 16;
                af[mt][0] = f2t(ab[(r + g)     * GS + ks * 8 + q]);
                af[mt][1] = f2t(ab[(r + g + 8) * GS + ks * 8 + q]);
                af[mt][2] = f2t(ab[(r + g)     * GS + ks * 8 + q + 4]);
                af[mt][3] = f2t(ab[(r + g + 8) * GS + ks * 8 + q + 4]);
            }
#pragma unroll
            for (int nt = 0; nt < 8; nt++) {
                int c = wc * 64 + nt * 8;
                bf[nt][0] = f2t(bb[(c + g) * GS + ks * 8 + q]);
                bf[nt][1] = f2t(bb[(c + g) * GS + ks * 8 + q + 4]);
            }
#pragma unroll
            for (int mt = 0; mt < 2; mt++)
#pragma unroll
                for (int nt = 0; nt < 8; nt++)
                    mma8(acc[mt][nt], af[mt], bf[nt]);
        }
        __syncthreads();
    }

#pragma unroll
    for (int mt = 0; mt < 2; mt++) {
        int r = bm + wr * 32 + mt * 16 + g;
#pragma unroll
        for (int nt = 0; nt < 8; nt++) {
            int cc = bn + wc * 64 + nt * 8 + 2 * q;
            float b0 = 0.0f, b1 = 0.0f;
            if (BIAS) { b0 = bias[cc]; b1 = bias[cc + 1]; }
            *(float2*)(C + (size_t)r * N + cc) =
                make_float2(acc[mt][nt][0] + b0, acc[mt][nt][1] + b1);
            *(float2*)(C + (size_t)(r + 8) * N + cc) =
                make_float2(acc[mt][nt][2] + b0, acc[mt][nt][3] + b1);
        }
    }
}

// ---------------- flash attention v4: pre-rounded tf32 operands ----------------
// 128 queries x 1 head; 8 warps x 16 rows. K/V cp.async double-buffered.
// All fragment loads are plain LDS (data already tf32). P bridged via shfl.
#define SQ 68
#define SK 68
#define SV 72
#define NT (SEQ / 64)
#define FLASH_SMEM ((128*SQ + 2*64*SK + 2*64*SV) * 4)   // 106496 B

__global__ void __launch_bounds__(256, 2)
flash_tc(float* __restrict__ out) {
    extern __shared__ char smraw[];
    float* Qs = (float*)smraw;                 // [128][SQ] tf32 bits
    float* Kb = (float*)(smraw + 128 * SQ * 4);
    float* Vb = Kb + 2 * 64 * SK;

    const int tid = threadIdx.x, lane = tid & 31, wid = tid >> 5;
    const int g = lane >> 2, q = lane & 3;
    const int bh = blockIdx.y, qt = blockIdx.x;
    const size_t base = (size_t)bh * SEQ * DH;
    const float* qg = g_q + base + (size_t)qt * 128 * DH;
    const float* kg0 = g_k + base;
    const float* vg0 = g_v + base;
    const int lrow = tid >> 4, lcol = (tid & 15) * 4;

    // stage Q via cp.async (8 passes cover 128x64)
#pragma unroll
    for (int j = 0; j < 8; j++) {
        int row = lrow + j * 16;
        cpa16(Qs + row * SQ + lcol, qg + row * DH + lcol);
    }
    cpa_commit();

    auto stage = [&](int buf, int kt) {
        float* kb = Kb + buf * 64 * SK;
        float* vb = Vb + buf * 64 * SV;
        const float* kg = kg0 + (size_t)kt * 64 * DH;
        const float* vg = vg0 + (size_t)kt * 64 * DH;
#pragma unroll
        for (int j = 0; j < 4; j++) {
            int row = lrow + j * 16;
            cpa16(kb + row * SK + lcol, kg + row * DH + lcol);
            cpa16(vb + row * SV + lcol, vg + row * DH + lcol);
        }
        cpa_commit();
    };

    float o[8][4];
#pragma unroll
    for (int nt = 0; nt < 8; nt++)
#pragma unroll
        for (int i = 0; i < 4; i++) o[nt][i] = 0.0f;
    float m0 = -1e30f, m1 = -1e30f, l0 = 0.0f, l1 = 0.0f;
    const int qr = wid * 16;
    const int srcA = (lane & ~3) + (q >> 1);
    const int srcB = srcA + 2;
    const bool odd = q & 1;

    stage(0, 0);
    for (int kt = 0; kt < NT; kt++) {
        int cur = kt & 1;
        if (kt + 1 < NT) { stage(cur ^ 1, kt + 1); cpa_wait<1>(); }
        else             { cpa_wait<0>(); }
        __syncthreads();
        const float* kb = Kb + cur * 64 * SK;
        const float* vb = Vb + cur * 64 * SV;

        // S = Q K^T (warp: 16x64) — all operands pre-rounded tf32
        float s[8][4];
#pragma unroll
        for (int nt = 0; nt < 8; nt++)
#pragma unroll
            for (int i = 0; i < 4; i++) s[nt][i] = 0.0f;
#pragma unroll
        for (int kc = 0; kc < 8; kc++) {
            unsigned af[4];
            af[0] = __float_as_uint(Qs[(qr + g)     * SQ + kc * 8 + q]);
            af[1] = __float_as_uint(Qs[(qr + g + 8) * SQ + kc * 8 + q]);
            af[2] = __float_as_uint(Qs[(qr + g)     * SQ + kc * 8 + q + 4]);
            af[3] = __float_as_uint(Qs[(qr + g + 8) * SQ + kc * 8 + q + 4]);
#pragma unroll
            for (int nt = 0; nt < 8; nt++) {
                unsigned bf[2];
                bf[0] = __float_as_uint(kb[(nt * 8 + g) * SK + kc * 8 + q]);
                bf[1] = __float_as_uint(kb[(nt * 8 + g) * SK + kc * 8 + q + 4]);
                mma8(s[nt], af, bf);
            }
        }

        // online softmax (scale already folded into Q)
        float rm0 = -1e30f, rm1 = -1e30f;
#pragma unroll
        for (int nt = 0; nt < 8; nt++) {
            rm0 = fmaxf(rm0, fmaxf(s[nt][0], s[nt][1]));
            rm1 = fmaxf(rm1, fmaxf(s[nt][2], s[nt][3]));
        }
        rm0 = fmaxf(rm0, __shfl_xor_sync(0xffffffffu, rm0, 1));
        rm0 = fmaxf(rm0, __shfl_xor_sync(0xffffffffu, rm0, 2));
        rm1 = fmaxf(rm1, __shfl_xor_sync(0xffffffffu, rm1, 1));
        rm1 = fmaxf(rm1, __shfl_xor_sync(0xffffffffu, rm1, 2));
        float mn0 = fmaxf(m0, rm0), mn1 = fmaxf(m1, rm1);
        float c0 = __expf(m0 - mn0), c1 = __expf(m1 - mn1);
        m0 = mn0; m1 = mn1;
        float rs0 = 0.0f, rs1 = 0.0f;
#pragma unroll
        for (int nt = 0; nt < 8; nt++) {
            s[nt][0] = __expf(s[nt][0] - mn0);
            s[nt][1] = __expf(s[nt][1] - mn0);
            s[nt][2] = __expf(s[nt][2] - mn1);
            s[nt][3] = __expf(s[nt][3] - mn1);
            rs0 += s[nt][0] + s[nt][1];
            rs1 += s[nt][2] + s[nt][3];
        }
        rs0 += __shfl_xor_sync(0xffffffffu, rs0, 1);
        rs0 += __shfl_xor_sync(0xffffffffu, rs0, 2);
        rs1 += __shfl_xor_sync(0xffffffffu, rs1, 1);
        rs1 += __shfl_xor_sync(0xffffffffu, rs1, 2);
        l0 = l0 * c0 + rs0;
        l1 = l1 * c1 + rs1;
#pragma unroll
        for (int nt = 0; nt < 8; nt++) {
            o[nt][0] *= c0; o[nt][1] *= c0; o[nt][2] *= c1; o[nt][3] *= c1;
        }

        // O += P V  — P fragments via shfl (C-layout -> A-layout)
#pragma unroll
        for (int kc = 0; kc < 8; kc++) {
            float e0 = __shfl_sync(0xffffffffu, s[kc][0], srcA);
            float e1 = __shfl_sync(0xffffffffu, s[kc][1], srcA);
            float e2 = __shfl_sync(0xffffffffu, s[kc][2], srcA);
            float e3 = __shfl_sync(0xffffffffu, s[kc][3], srcA);
            float f0 = __shfl_sync(0xffffffffu, s[kc][0], srcB);
            float f1 = __shfl_sync(0xffffffffu, s[kc][1], srcB);
            float f2 = __shfl_sync(0xffffffffu, s[kc][2], srcB);
            float f3 = __shfl_sync(0xffffffffu, s[kc][3], srcB);
            unsigned af[4];
            af[0] = f2t(odd ? e1 : e0);
            af[1] = f2t(odd ? e3 : e2);
            af[2] = f2t(odd ? f1 : f0);
            af[3] = f2t(odd ? f3 : f2);
#pragma unroll
            for (int nt = 0; nt < 8; nt++) {
                unsigned bf[2];
                bf[0] = __float_as_uint(vb[(kc * 8 + q)     * SV + nt * 8 + g]);
                bf[1] = __float_as_uint(vb[(kc * 8 + q + 4) * SV + nt * 8 + g]);
                mma8(o[nt], af, bf);
            }
        }
        __syncthreads();
    }

    // epilogue
    int b = bh >> 4, h = bh & 15;
    float il0 = 1.0f / l0, il1 = 1.0f / l1;
    int r0 = qt * 128 + qr + g;
#pragma unroll
    for (int nt = 0; nt < 8; nt++) {
        int cc = h * DH + nt * 8 + 2 * q;
        *(float2*)(out + (size_t)(b * SEQ + r0) * INNER + cc) =
            make_float2(o[nt][0] * il0, o[nt][1] * il0);
        *(float2*)(out + (size_t)(b * SEQ + r0 + 8) * INNER + cc) =
            make_float2(o[nt][2] * il1, o[nt][3] * il1);
    }
}

// ---------------- launch ----------------
extern "C" void kernel_launch(void* const* d_in, const int* in_sizes, int n_in,
                              void* d_out, int out_size) {
    const float* x       = (const float*)d_in[0];
    const float* w_qkv   = (const float*)d_in[1];
    const float* w_fproj = (const float*)d_in[2];
    const float* b_fproj = (const float*)d_in[3];
    const float* w_out   = (const float*)d_in[4];
    const float* b_out   = (const float*)d_in[5];
    float* out = (float*)d_out;

    float *qkv_p, *attn_p;
    cudaGetSymbolAddress((void**)&qkv_p,  g_qkv);
    cudaGetSymbolAddress((void**)&attn_p, g_attn);

    cudaFuncSetAttribute(gemm_tf32<false>, cudaFuncAttributeMaxDynamicSharedMemorySize, GEMM_SMEM);
    cudaFuncSetAttribute(gemm_tf32<true>,  cudaFuncAttributeMaxDynamicSharedMemorySize, GEMM_SMEM);
    cudaFuncSetAttribute(flash_tc, cudaFuncAttributeMaxDynamicSharedMemorySize, FLASH_SMEM);

    table_kernel<<<SEQ, DH>>>(w_fproj, b_fproj);

    {   // QKV: [8192,3072] = x @ w_qkv^T
        dim3 grid(3 * INNER / 128, ROWS / 128);
        gemm_tf32<false><<<grid, 256, GEMM_SMEM>>>(x, w_qkv, nullptr, qkv_p, ROWS, 3 * INNER, DIM);
    }

    rope_kernel<<<(BATCH * SEQ * HEADS * DH) / 256, 256>>>();

    {   // flash attention
        dim3 grid(SEQ / 128, BH);
        flash_tc<<<grid, 256, FLASH_SMEM>>>(attn_p);
    }

    {   // out projection
        dim3 grid(DIM / 128, ROWS / 128);
        gemm_tf32<true><<<grid, 256, GEMM_SMEM>>>(attn_p, w_out, b_out, out, ROWS, DIM, INNER);
    }
}

// round 6
// speedup vs baseline: 3.8987x; 1.0560x over previous
#include <cuda_runtime.h>
#include <cuda_bf16.h>
#include <math.h>
#include <cstdint>

#define BATCH 4
#define SEQ   2048
#define DIM   1024
#define HEADS 16
#define DH    64
#define INNER 1024
#define NFREQ 16
#define ROWS  (BATCH*SEQ)     // 8192
#define BH    (BATCH*HEADS)   // 64

// ---------------- scratch ----------------
__device__ float g_qkv [(size_t)ROWS * 3 * INNER];
__device__ float g_q   [(size_t)BH * SEQ * DH];   // tf32-rounded, pre-scaled by 1/8
__device__ float g_k   [(size_t)BH * SEQ * DH];   // tf32-rounded
__device__ float g_v   [(size_t)BH * SEQ * DH];   // tf32-rounded
__device__ float g_attn[(size_t)ROWS * INNER];
__device__ float g_fenc[SEQ * DH];
__device__ float g_sinv[SEQ * 32];
__device__ float g_cosv[SEQ * 32];

// ---------------- helpers ----------------
__device__ __forceinline__ unsigned f2t(float x) {
    unsigned u; asm("cvt.rna.tf32.f32 %0, %1;" : "=r"(u) : "f"(x)); return u;
}
__device__ __forceinline__ void mma8(float* c, const unsigned* a, const unsigned* b) {
    asm volatile(
        "mma.sync.aligned.m16n8k8.row.col.f32.tf32.tf32.f32 "
        "{%0,%1,%2,%3},{%4,%5,%6,%7},{%8,%9},{%0,%1,%2,%3};"
        : "+f"(c[0]), "+f"(c[1]), "+f"(c[2]), "+f"(c[3])
        : "r"(a[0]), "r"(a[1]), "r"(a[2]), "r"(a[3]), "r"(b[0]), "r"(b[1]));
}
__device__ __forceinline__ void cpa16(void* smem, const void* gmem) {
    unsigned s = (unsigned)__cvta_generic_to_shared(smem);
    asm volatile("cp.async.cg.shared.global [%0], [%1], 16;" :: "r"(s), "l"(gmem));
}
__device__ __forceinline__ void cpa_commit() { asm volatile("cp.async.commit_group;"); }
template<int N> __device__ __forceinline__ void cpa_wait() {
    asm volatile("cp.async.wait_group %0;" :: "n"(N));
}

// ---------------- table kernel ----------------
__global__ void table_kernel(const float* __restrict__ w_fproj,
                             const float* __restrict__ b_fproj) {
    int p = blockIdx.x;
    int d = threadIdx.x;
    float fp = (float)p;
    float acc = b_fproj[d];
#pragma unroll
    for (int j = 0; j < NFREQ; j++) {
        float s = sinf(fp * (float)(j + 1));
        float c = cosf(fp * (float)(j + 1));
        acc += s * w_fproj[d * (2 * NFREQ) + j] + c * w_fproj[d * (2 * NFREQ) + NFREQ + j];
    }
    g_fenc[p * DH + d] = acc;
    if (d < 32) {
        float freq = powf(10000.0f, -(float)d / 32.0f);
        float ang = fp * freq;
        g_sinv[p * 32 + d] = sinf(ang);
        g_cosv[p * 32 + d] = cosf(ang);
    }
}

// ---------------- RoPE + rearrange + tf32 pre-round ----------------
__global__ void __launch_bounds__(256)
rope_kernel() {
    int idx = blockIdx.x * 256 + threadIdx.x;
    int d = idx & 63;
    int h = (idx >> 6) & 15;
    int n = (idx >> 10) & 2047;
    int b = idx >> 21;
    const float* row = g_qkv + (size_t)(b * SEQ + n) * (3 * INNER);
    int col = h * DH + d;
    float cosv = g_cosv[n * 32 + (d >> 1)];
    float sinv = g_sinv[n * 32 + (d >> 1)];
    float fe   = g_fenc[n * DH + d];
    int pidx; float sgn;
    if (d < 32) { pidx = 2 * d + 1;    sgn = -1.0f; }
    else        { pidx = 2 * (d - 32); sgn =  1.0f; }
    float qv = row[col];
    float qp = row[h * DH + pidx];
    float kv = row[INNER + col];
    float kp = row[INNER + h * DH + pidx];
    float vv = row[2 * INNER + col];
    int bh = b * HEADS + h;
    size_t o = ((size_t)bh * SEQ + n) * DH + d;
    g_q[o] = __uint_as_float(f2t(0.125f * (qv * cosv + sgn * qp * sinv + fe)));
    g_k[o] = __uint_as_float(f2t(kv * cosv + sgn * kp * sinv + fe));
    g_v[o] = __uint_as_float(f2t(vv));
}

// ---------------- tf32 GEMM, cp.async double-buffered (unchanged) ----------------
#define GS 20
#define GEMM_SMEM (2 * 2 * 128 * GS * 4)   // 81920 B

template<bool BIAS>
__global__ void __launch_bounds__(256, 2)
gemm_tf32(const float* __restrict__ A, const float* __restrict__ Bw,
          const float* __restrict__ bias, float* __restrict__ C,
          int M, int N, int K) {
    extern __shared__ float gsm[];
    float* As = gsm;
    float* Bs = gsm + 2 * 128 * GS;
    const int tid = threadIdx.x;
    const int lane = tid & 31, wid = tid >> 5;
    const int g = lane >> 2, q = lane & 3;
    const int wr = wid >> 1, wc = wid & 1;
    const int bm = blockIdx.y * 128, bn = blockIdx.x * 128;
    const int lrow = tid >> 2, lcol = (tid & 3) * 4;
    const int lrow2 = lrow + 64;

    float acc[2][8][4];
#pragma unroll
    for (int mt = 0; mt < 2; mt++)
#pragma unroll
        for (int nt = 0; nt < 8; nt++)
#pragma unroll
            for (int i = 0; i < 4; i++) acc[mt][nt][i] = 0.0f;

    auto stage = [&](int buf, int k0) {
        float* ab = As + buf * 128 * GS;
        float* bb = Bs + buf * 128 * GS;
        cpa16(ab + lrow  * GS + lcol, A  + (size_t)(bm + lrow)  * K + k0 + lcol);
        cpa16(ab + lrow2 * GS + lcol, A  + (size_t)(bm + lrow2) * K + k0 + lcol);
        cpa16(bb + lrow  * GS + lcol, Bw + (size_t)(bn + lrow)  * K + k0 + lcol);
        cpa16(bb + lrow2 * GS + lcol, Bw + (size_t)(bn + lrow2) * K + k0 + lcol);
        cpa_commit();
    };

    stage(0, 0);
    for (int k0 = 0; k0 < K; k0 += 16) {
        int cur = (k0 >> 4) & 1;
        if (k0 + 16 < K) { stage(cur ^ 1, k0 + 16); cpa_wait<1>(); }
        else             { cpa_wait<0>(); }
        __syncthreads();
        const float* ab = As + cur * 128 * GS;
        const float* bb = Bs + cur * 128 * GS;
#pragma unroll
        for (int ks = 0; ks < 2; ks++) {
            unsigned af[2][4], bf[8][2];
#pragma unroll
            for (int mt = 0; mt < 2; mt++) {
                int r = wr * 32 + mt * 16;
                af[mt][0] = f2t(ab[(r + g)     * GS + ks * 8 + q]);
                af[mt][1] = f2t(ab[(r + g + 8) * GS + ks * 8 + q]);
                af[mt][2] = f2t(ab[(r + g)     * GS + ks * 8 + q + 4]);
                af[mt][3] = f2t(ab[(r + g + 8) * GS + ks * 8 + q + 4]);
            }
#pragma unroll
            for (int nt = 0; nt < 8; nt++) {
                int c = wc * 64 + nt * 8;
                bf[nt][0] = f2t(bb[(c + g) * GS + ks * 8 + q]);
                bf[nt][1] = f2t(bb[(c + g) * GS + ks * 8 + q + 4]);
            }
#pragma unroll
            for (int mt = 0; mt < 2; mt++)
#pragma unroll
                for (int nt = 0; nt < 8; nt++)
                    mma8(acc[mt][nt], af[mt], bf[nt]);
        }
        __syncthreads();
    }

#pragma unroll
    for (int mt = 0; mt < 2; mt++) {
        int r = bm + wr * 32 + mt * 16 + g;
#pragma unroll
        for (int nt = 0; nt < 8; nt++) {
            int cc = bn + wc * 64 + nt * 8 + 2 * q;
            float b0 = 0.0f, b1 = 0.0f;
            if (BIAS) { b0 = bias[cc]; b1 = bias[cc + 1]; }
            *(float2*)(C + (size_t)r * N + cc) =
                make_float2(acc[mt][nt][0] + b0, acc[mt][nt][1] + b1);
            *(float2*)(C + (size_t)(r + 8) * N + cc) =
                make_float2(acc[mt][nt][2] + b0, acc[mt][nt][3] + b1);
        }
    }
}

// ---------------- flash attention v5: 4 warps x 32-query tiles ----------------
// block: 128 threads, 128 queries; warp owns 32 query rows (mt=0,1).
// K/V B-fragments loaded once per kc, reused across both mt sub-tiles.
#define SQ 68
#define SK 68
#define SV 72
#define NT (SEQ / 64)
#define FLASH_SMEM ((128*SQ + 2*64*SK + 2*64*SV) * 4)   // 106496 B

__global__ void __launch_bounds__(128, 2)
flash_tc(float* __restrict__ out) {
    extern __shared__ char smraw[];
    float* Qs = (float*)smraw;                 // [128][SQ] tf32 bits
    float* Kb = (float*)(smraw + 128 * SQ * 4);
    float* Vb = Kb + 2 * 64 * SK;

    const int tid = threadIdx.x, lane = tid & 31, wid = tid >> 5;
    const int g = lane >> 2, q = lane & 3;
    const int bh = blockIdx.y, qt = blockIdx.x;
    const size_t base = (size_t)bh * SEQ * DH;
    const float* qg = g_q + base + (size_t)qt * 128 * DH;
    const float* kg0 = g_k + base;
    const float* vg0 = g_v + base;
    const int lrow = tid >> 4, lcol = (tid & 15) * 4;   // lrow 0..7

    // stage Q via cp.async (16 passes cover 128x64 with 128 threads)
#pragma unroll
    for (int j = 0; j < 16; j++) {
        int row = lrow + j * 8;
        cpa16(Qs + row * SQ + lcol, qg + row * DH + lcol);
    }
    cpa_commit();

    auto stage = [&](int buf, int kt) {
        float* kb = Kb + buf * 64 * SK;
        float* vb = Vb + buf * 64 * SV;
        const float* kg = kg0 + (size_t)kt * 64 * DH;
        const float* vg = vg0 + (size_t)kt * 64 * DH;
#pragma unroll
        for (int j = 0; j < 8; j++) {
            int row = lrow + j * 8;
            cpa16(kb + row * SK + lcol, kg + row * DH + lcol);
            cpa16(vb + row * SV + lcol, vg + row * DH + lcol);
        }
        cpa_commit();
    };

    float o[2][8][4];
#pragma unroll
    for (int mt = 0; mt < 2; mt++)
#pragma unroll
        for (int nt = 0; nt < 8; nt++)
#pragma unroll
            for (int i = 0; i < 4; i++) o[mt][nt][i] = 0.0f;
    float m0[2] = {-1e30f, -1e30f}, m1[2] = {-1e30f, -1e30f};
    float l0[2] = {0.0f, 0.0f},     l1[2] = {0.0f, 0.0f};
    const int qr = wid * 32;
    const int srcA = (lane & ~3) + (q >> 1);
    const int srcB = srcA + 2;
    const bool odd = q & 1;

    stage(0, 0);
    for (int kt = 0; kt < NT; kt++) {
        int cur = kt & 1;
        if (kt + 1 < NT) { stage(cur ^ 1, kt + 1); cpa_wait<1>(); }
        else             { cpa_wait<0>(); }
        __syncthreads();
        const float* kb = Kb + cur * 64 * SK;
        const float* vb = Vb + cur * 64 * SV;

        // S = Q K^T  (warp: 32x64) — K fragments shared across both mt tiles
        float s[2][8][4];
#pragma unroll
        for (int mt = 0; mt < 2; mt++)
#pragma unroll
            for (int nt = 0; nt < 8; nt++)
#pragma unroll
                for (int i = 0; i < 4; i++) s[mt][nt][i] = 0.0f;
#pragma unroll
        for (int kc = 0; kc < 8; kc++) {
            unsigned bf[8][2];
#pragma unroll
            for (int nt = 0; nt < 8; nt++) {
                bf[nt][0] = __float_as_uint(kb[(nt * 8 + g) * SK + kc * 8 + q]);
                bf[nt][1] = __float_as_uint(kb[(nt * 8 + g) * SK + kc * 8 + q + 4]);
            }
#pragma unroll
            for (int mt = 0; mt < 2; mt++) {
                int r = qr + mt * 16;
                unsigned af[4];
                af[0] = __float_as_uint(Qs[(r + g)     * SQ + kc * 8 + q]);
                af[1] = __float_as_uint(Qs[(r + g + 8) * SQ + kc * 8 + q]);
                af[2] = __float_as_uint(Qs[(r + g)     * SQ + kc * 8 + q + 4]);
                af[3] = __float_as_uint(Qs[(r + g + 8) * SQ + kc * 8 + q + 4]);
#pragma unroll
                for (int nt = 0; nt < 8; nt++)
                    mma8(s[mt][nt], af, bf[nt]);
            }
        }

        // online softmax per mt tile (scale folded into Q upstream)
#pragma unroll
        for (int mt = 0; mt < 2; mt++) {
            float rm0 = -1e30f, rm1 = -1e30f;
#pragma unroll
            for (int nt = 0; nt < 8; nt++) {
                rm0 = fmaxf(rm0, fmaxf(s[mt][nt][0], s[mt][nt][1]));
                rm1 = fmaxf(rm1, fmaxf(s[mt][nt][2], s[mt][nt][3]));
            }
            rm0 = fmaxf(rm0, __shfl_xor_sync(0xffffffffu, rm0, 1));
            rm0 = fmaxf(rm0, __shfl_xor_sync(0xffffffffu, rm0, 2));
            rm1 = fmaxf(rm1, __shfl_xor_sync(0xffffffffu, rm1, 1));
            rm1 = fmaxf(rm1, __shfl_xor_sync(0xffffffffu, rm1, 2));
            float mn0 = fmaxf(m0[mt], rm0), mn1 = fmaxf(m1[mt], rm1);
            float c0 = __expf(m0[mt] - mn0), c1 = __expf(m1[mt] - mn1);
            m0[mt] = mn0; m1[mt] = mn1;
            float rs0 = 0.0f, rs1 = 0.0f;
#pragma unroll
            for (int nt = 0; nt < 8; nt++) {
                s[mt][nt][0] = __expf(s[mt][nt][0] - mn0);
                s[mt][nt][1] = __expf(s[mt][nt][1] - mn0);
                s[mt][nt][2] = __expf(s[mt][nt][2] - mn1);
                s[mt][nt][3] = __expf(s[mt][nt][3] - mn1);
                rs0 += s[mt][nt][0] + s[mt][nt][1];
                rs1 += s[mt][nt][2] + s[mt][nt][3];
            }
            rs0 += __shfl_xor_sync(0xffffffffu, rs0, 1);
            rs0 += __shfl_xor_sync(0xffffffffu, rs0, 2);
            rs1 += __shfl_xor_sync(0xffffffffu, rs1, 1);
            rs1 += __shfl_xor_sync(0xffffffffu, rs1, 2);
            l0[mt] = l0[mt] * c0 + rs0;
            l1[mt] = l1[mt] * c1 + rs1;
#pragma unroll
            for (int nt = 0; nt < 8; nt++) {
                o[mt][nt][0] *= c0; o[mt][nt][1] *= c0;
                o[mt][nt][2] *= c1; o[mt][nt][3] *= c1;
            }
        }

        // O += P V  — V fragments shared across both mt tiles; P via shfl bridge
#pragma unroll
        for (int kc = 0; kc < 8; kc++) {
            unsigned bfv[8][2];
#pragma unroll
            for (int nt = 0; nt < 8; nt++) {
                bfv[nt][0] = __float_as_uint(vb[(kc * 8 + q)     * SV + nt * 8 + g]);
                bfv[nt][1] = __float_as_uint(vb[(kc * 8 + q + 4) * SV + nt * 8 + g]);
            }
#pragma unroll
            for (int mt = 0; mt < 2; mt++) {
                float e0 = __shfl_sync(0xffffffffu, s[mt][kc][0], srcA);
                float e1 = __shfl_sync(0xffffffffu, s[mt][kc][1], srcA);
                float e2 = __shfl_sync(0xffffffffu, s[mt][kc][2], srcA);
                float e3 = __shfl_sync(0xffffffffu, s[mt][kc][3], srcA);
                float f0 = __shfl_sync(0xffffffffu, s[mt][kc][0], srcB);
                float f1 = __shfl_sync(0xffffffffu, s[mt][kc][1], srcB);
                float f2 = __shfl_sync(0xffffffffu, s[mt][kc][2], srcB);
                float f3 = __shfl_sync(0xffffffffu, s[mt][kc][3], srcB);
                unsigned af[4];
                af[0] = f2t(odd ? e1 : e0);
                af[1] = f2t(odd ? e3 : e2);
                af[2] = f2t(odd ? f1 : f0);
                af[3] = f2t(odd ? f3 : f2);
#pragma unroll
                for (int nt = 0; nt < 8; nt++)
                    mma8(o[mt][nt], af, bfv[nt]);
            }
        }
        __syncthreads();
    }

    // epilogue
    int b = bh >> 4, h = bh & 15;
#pragma unroll
    for (int mt = 0; mt < 2; mt++) {
        float il0 = 1.0f / l0[mt], il1 = 1.0f / l1[mt];
        int r0 = qt * 128 + qr + mt * 16 + g;
#pragma unroll
        for (int nt = 0; nt < 8; nt++) {
            int cc = h * DH + nt * 8 + 2 * q;
            *(float2*)(out + (size_t)(b * SEQ + r0) * INNER + cc) =
                make_float2(o[mt][nt][0] * il0, o[mt][nt][1] * il0);
            *(float2*)(out + (size_t)(b * SEQ + r0 + 8) * INNER + cc) =
                make_float2(o[mt][nt][2] * il1, o[mt][nt][3] * il1);
        }
    }
}

// ---------------- launch ----------------
extern "C" void kernel_launch(void* const* d_in, const int* in_sizes, int n_in,
                              void* d_out, int out_size) {
    const float* x       = (const float*)d_in[0];
    const float* w_qkv   = (const float*)d_in[1];
    const float* w_fproj = (const float*)d_in[2];
    const float* b_fproj = (const float*)d_in[3];
    const float* w_out   = (const float*)d_in[4];
    const float* b_out   = (const float*)d_in[5];
    float* out = (float*)d_out;

    float *qkv_p, *attn_p;
    cudaGetSymbolAddress((void**)&qkv_p,  g_qkv);
    cudaGetSymbolAddress((void**)&attn_p, g_attn);

    cudaFuncSetAttribute(gemm_tf32<false>, cudaFuncAttributeMaxDynamicSharedMemorySize, GEMM_SMEM);
    cudaFuncSetAttribute(gemm_tf32<true>,  cudaFuncAttributeMaxDynamicSharedMemorySize, GEMM_SMEM);
    cudaFuncSetAttribute(flash_tc, cudaFuncAttributeMaxDynamicSharedMemorySize, FLASH_SMEM);

    table_kernel<<<SEQ, DH>>>(w_fproj, b_fproj);

    {   // QKV: [8192,3072] = x @ w_qkv^T
        dim3 grid(3 * INNER / 128, ROWS / 128);
        gemm_tf32<false><<<grid, 256, GEMM_SMEM>>>(x, w_qkv, nullptr, qkv_p, ROWS, 3 * INNER, DIM);
    }

    rope_kernel<<<(BATCH * SEQ * HEADS * DH) / 256, 256>>>();

    {   // flash attention
        dim3 grid(SEQ / 128, BH);
        flash_tc<<<grid, 128, FLASH_SMEM>>>(attn_p);
    }

    {   // out projection
        dim3 grid(DIM / 128, ROWS / 128);
        gemm_tf32<true><<<grid, 256, GEMM_SMEM>>>(attn_p, w_out, b_out, out, ROWS, DIM, INNER);
    }
}